// round 12
// baseline (speedup 1.0000x reference)
#include <cuda_runtime.h>
#include <math.h>

// ChamferLoss_31044023616212: one-sided Chamfer distance
//   set1: [2, 8192, 3] f32, set2: [2, 8192, 3] f32 -> scalar f32
//
// Exact z-bucket pruning, WARP-COHERENT version.
//  * prep kernel buckets BOTH sets by z (512 bins). set1 keeps orig index.
//  * search warp = 32 consecutive z-sorted x points; the whole warp scans
//    one shared candidate range (same address -> broadcast loads, L1-hot),
//    each lane min-accumulating for its own x. Expansion decided by
//    __any_sync (warp-uniform control; no masked serialization).
//  * stop a direction when (bucket near-edge dz)^2 >= best_m + |x|^2
//    (exact z lower bound). Scanning a superset never changes the min ->
//    per-point result is the exact global min, independent of scatter order.
//  * distances stored to g_dist[orig index]; fixed-order final sum in the
//    last finishing block -> deterministic output.
// m = |y|^2 - 2<x,y>;  d = sqrt(max(min m + |x|^2, 0))  (reference identity)

#define NBATCH 2
#define NB     512
#define ZMIN   (-6.0f)
#define ZWID   (12.0f / NB)
#define ZINV   (NB / 12.0f)
#define NMAX   8192
#define ST     128                  // search threads per block

__device__ float4 g_y[NBATCH][NMAX];       // sorted set2: (y0,y1,y2,|y|^2)
__device__ int    g_yoff[NBATCH][NB + 1];  // set2 bucket offsets
__device__ float4 g_x[NBATCH][NMAX];       // sorted set1: (x0,x1,x2,orig_idx)
__device__ float  g_dist[NBATCH * NMAX];   // per-point NN distance (orig order)
__device__ int    g_count = 0;

// ---------------- kernel 1: bucket both sets by z ----------------
extern "C" __global__ void __launch_bounds__(1024, 1)
bucket_kernel(const float* __restrict__ set1,
              const float* __restrict__ set2, int n)
{
    __shared__ int hist[NB];
    __shared__ int offs[NB + 1];
    __shared__ int cur[NB];

    const int  job = blockIdx.x;        // 0,1: set2 b=0,1   2,3: set1 b=0,1
    const int  b   = job & 1;
    const bool isX = (job >> 1) != 0;
    const float* src = (isX ? set1 : set2) + (size_t)b * n * 3;
    const int tid = threadIdx.x;

    for (int i = tid; i < NB; i += 1024) hist[i] = 0;
    __syncthreads();

    for (int j = tid; j < n; j += 1024) {
        float z = src[3 * j + 2];
        int ib = min(max((int)((z - ZMIN) * ZINV), 0), NB - 1);
        atomicAdd(&hist[ib], 1);
    }
    __syncthreads();

    // exclusive prefix (Hillis-Steele over 512 entries)
    if (tid < NB) offs[tid + 1] = hist[tid];
    if (tid == 0) offs[0] = 0;
    __syncthreads();
    for (int s = 1; s < NB; s <<= 1) {
        int add = 0;
        if (tid < NB && tid >= s) add = offs[tid + 1 - s];
        __syncthreads();
        if (tid < NB) offs[tid + 1] += add;
        __syncthreads();
    }
    if (tid < NB) cur[tid] = offs[tid];
    __syncthreads();

    for (int j = tid; j < n; j += 1024) {
        float v0 = src[3 * j + 0];
        float v1 = src[3 * j + 1];
        float v2 = src[3 * j + 2];
        int ib = min(max((int)((v2 - ZMIN) * ZINV), 0), NB - 1);
        int r = atomicAdd(&cur[ib], 1);
        if (isX) g_x[b][r] = make_float4(v0, v1, v2, __int_as_float(j));
        else     g_y[b][r] = make_float4(v0, v1, v2, v0*v0 + v1*v1 + v2*v2);
    }

    if (!isX) {
        if (tid < NB) g_yoff[b][tid] = offs[tid];
        if (tid == 0) g_yoff[b][NB] = offs[NB];
    }
}

// scan Y[r..e) with 2 independent FMA chains, min into best
__device__ __forceinline__ float scan_range(const float4* __restrict__ Y,
                                            int r, int e,
                                            float x0, float x1, float x2,
                                            float best)
{
    float b0 = best, b1 = 3.4e38f;
    for (; r + 1 < e; r += 2) {
        float4 qa = Y[r], qb = Y[r + 1];
        float da = fmaf(x0, qa.x, fmaf(x1, qa.y, x2 * qa.z));
        float db = fmaf(x0, qb.x, fmaf(x1, qb.y, x2 * qb.z));
        b0 = fminf(b0, fmaf(-2.0f, da, qa.w));
        b1 = fminf(b1, fmaf(-2.0f, db, qb.w));
    }
    if (r < e) {
        float4 q = Y[r];
        float d = fmaf(x0, q.x, fmaf(x1, q.y, x2 * q.z));
        b0 = fminf(b0, fmaf(-2.0f, d, q.w));
    }
    return fminf(b0, b1);
}

// ---------------- kernel 2: warp-coherent pruned search ----------------
extern "C" __global__ void __launch_bounds__(ST, 1)
search_kernel(float* __restrict__ out, int n, int nblk)
{
    __shared__ int   soff[NB + 1];
    __shared__ float buf[ST];
    __shared__ bool  amLast;

    const int tid = threadIdx.x;
    const int bx  = blockIdx.x;
    const int b   = blockIdx.y;

    for (int i = tid; i <= NB; i += ST) soff[i] = g_yoff[b][i];
    __syncthreads();

    // this thread's sorted set1 point
    const int pos = bx * ST + tid;
    float4 X = g_x[b][pos];
    const float x0 = X.x, x1 = X.y, x2 = X.z;
    const int   orig = __float_as_int(X.w);
    const float sqx  = x0*x0 + x1*x1 + x2*x2;
    int xb = min(max((int)((x2 - ZMIN) * ZINV), 0), NB - 1);

    // warp-shared starting window [bmin, bmax]
    int bmin = xb, bmax = xb;
    #pragma unroll
    for (int o = 16; o > 0; o >>= 1) {
        bmin = min(bmin, __shfl_xor_sync(0xffffffffu, bmin, o));
        bmax = max(bmax, __shfl_xor_sync(0xffffffffu, bmax, o));
    }

    const float4* __restrict__ Y = g_y[b];
    float best = 3.4e38f;          // min over m = |y|^2 - 2<x,y>

    // initial contiguous scan (buckets are contiguous in memory)
    best = scan_range(Y, soff[bmin], soff[bmax + 1], x0, x1, x2, best);

    // outward expansion; direction continues while ANY lane still needs it
    int up = bmax + 1, dn = bmin - 1;
    for (;;) {
        bool wu = false, wd = false;
        if (up < NB) {
            float dz = (ZMIN + up * ZWID) - x2;          // >= 0
            wu = (dz * dz < best + sqx);
        }
        if (dn >= 0) {
            float dz = x2 - (ZMIN + (dn + 1) * ZWID);    // >= 0
            wd = (dz * dz < best + sqx);
        }
        bool anyU = __any_sync(0xffffffffu, wu);
        bool anyD = __any_sync(0xffffffffu, wd);
        if (!anyU && !anyD) break;
        if (anyU) {
            best = scan_range(Y, soff[up], soff[up + 1], x0, x1, x2, best);
            ++up;
        }
        if (anyD) {
            best = scan_range(Y, soff[dn], soff[dn + 1], x0, x1, x2, best);
            --dn;
        }
    }

    // exact NN distance, written to the ORIGINAL index -> deterministic sum
    g_dist[b * n + orig] = sqrtf(fmaxf(best + sqx, 0.0f));

    __threadfence();
    __syncthreads();
    if (tid == 0) amLast = (atomicAdd(&g_count, 1) == nblk - 1);
    __syncthreads();

    if (amLast) {
        // fixed-order final reduction over all points
        float s = 0.0f;
        const int total = NBATCH * n;
        for (int i = tid; i < total; i += ST) s += __ldcg(&g_dist[i]);
        buf[tid] = s;
        __syncthreads();
        #pragma unroll
        for (int st = ST / 2; st > 0; st >>= 1) {
            if (tid < st) buf[tid] += buf[tid + st];
            __syncthreads();
        }
        if (tid == 0) {
            out[0]  = buf[0];
            g_count = 0;           // self-reset for graph replay
        }
    }
}

extern "C" void kernel_launch(void* const* d_in, const int* in_sizes, int n_in,
                              void* d_out, int out_size)
{
    const float* set1 = (const float*)d_in[0];
    const float* set2 = (const float*)d_in[1];

    // in_sizes[0] = b * n * d = 2 * n * 3
    const int n = in_sizes[0] / (NBATCH * 3);
    const int sbx  = n / ST;              // search blocks per batch
    const int nblk = sbx * NBATCH;

    bucket_kernel<<<2 * NBATCH, 1024>>>(set1, set2, n);
    dim3 grid(sbx, NBATCH);
    search_kernel<<<grid, ST>>>((float*)d_out, n, nblk);
}

// round 13
// speedup vs baseline: 2.1040x; 2.1040x over previous
#include <cuda_runtime.h>
#include <math.h>

// ChamferLoss_31044023616212: one-sided Chamfer distance
//   set1: [2, 8192, 3] f32, set2: [2, 8192, 3] f32 -> scalar f32
//
// R13: exact z-bucket pruning executed with the brute-force (roofline)
// micro-pattern.  R11 failed (137us) because 1 thread/point = 3.5 warps/SM.
// Now: block = 128 consecutive z-sorted x points; phase A computes a cheap
// NN upper bound per point (+-3 buckets); block window [zmin-r, zmax+r]
// provably contains every point's true NN; phase B scans that contiguous
// window with 16 warp-uniform chunks x 4 register-resident points/thread
// (broadcast loads) -- the validated 36.9us inner pattern at ~9x less work.
// All mins are over bucket-SETS (scatter-order invariant) and the final sum
// is fixed-order -> deterministic.  m = |y|^2 - 2<x,y> identity throughout.

#define NBATCH 2
#define NB     512
#define ZMIN   (-6.0f)
#define ZWID   (12.0f / NB)
#define ZINV   (NB / 12.0f)
#define NMAX   8192
#define P      128                 // x points per search block
#define TS     512                 // search threads per block
#define NCH    16                  // window chunks (= warps)
#define RPAD   17

__device__ float4 g_y[NBATCH][NMAX];       // sorted set2: (y0,y1,y2,|y|^2)
__device__ int    g_yoff[NBATCH][NB + 1];  // set2 bucket offsets
__device__ float4 g_x[NBATCH][NMAX];       // sorted set1: (x0,x1,x2,orig_idx)
__device__ float  g_dist[NBATCH * NMAX];   // per-point NN distance (orig order)
__device__ int    g_count = 0;

// ---------------- kernel 1: bucket both sets by z (validated R12) ----------
extern "C" __global__ void __launch_bounds__(1024, 1)
bucket_kernel(const float* __restrict__ set1,
              const float* __restrict__ set2, int n)
{
    __shared__ int hist[NB];
    __shared__ int offs[NB + 1];
    __shared__ int cur[NB];

    const int  job = blockIdx.x;        // 0,1: set2 b=0,1   2,3: set1 b=0,1
    const int  b   = job & 1;
    const bool isX = (job >> 1) != 0;
    const float* src = (isX ? set1 : set2) + (size_t)b * n * 3;
    const int tid = threadIdx.x;

    for (int i = tid; i < NB; i += 1024) hist[i] = 0;
    __syncthreads();

    for (int j = tid; j < n; j += 1024) {
        float z = src[3 * j + 2];
        int ib = min(max((int)((z - ZMIN) * ZINV), 0), NB - 1);
        atomicAdd(&hist[ib], 1);
    }
    __syncthreads();

    if (tid < NB) offs[tid + 1] = hist[tid];
    if (tid == 0) offs[0] = 0;
    __syncthreads();
    for (int s = 1; s < NB; s <<= 1) {
        int add = 0;
        if (tid < NB && tid >= s) add = offs[tid + 1 - s];
        __syncthreads();
        if (tid < NB) offs[tid + 1] += add;
        __syncthreads();
    }
    if (tid < NB) cur[tid] = offs[tid];
    __syncthreads();

    for (int j = tid; j < n; j += 1024) {
        float v0 = src[3 * j + 0];
        float v1 = src[3 * j + 1];
        float v2 = src[3 * j + 2];
        int ib = min(max((int)((v2 - ZMIN) * ZINV), 0), NB - 1);
        int r = atomicAdd(&cur[ib], 1);
        if (isX) g_x[b][r] = make_float4(v0, v1, v2, __int_as_float(j));
        else     g_y[b][r] = make_float4(v0, v1, v2, v0*v0 + v1*v1 + v2*v2);
    }

    if (!isX) {
        if (tid < NB) g_yoff[b][tid] = offs[tid];
        if (tid == 0) g_yoff[b][NB] = offs[NB];
    }
}

__device__ __forceinline__ float mval(float4 q, float x0, float x1, float x2) {
    float d = fmaf(x0, q.x, fmaf(x1, q.y, x2 * q.z));
    return fmaf(-2.0f, d, q.w);
}

// serial scan of Y[r..e), 2 independent chains
__device__ __forceinline__ float scan_range(const float4* __restrict__ Y,
                                            int r, int e,
                                            float x0, float x1, float x2,
                                            float best)
{
    float b0 = best, b1 = 3.4e38f;
    for (; r + 1 < e; r += 2) {
        b0 = fminf(b0, mval(Y[r],     x0, x1, x2));
        b1 = fminf(b1, mval(Y[r + 1], x0, x1, x2));
    }
    if (r < e) b0 = fminf(b0, mval(Y[r], x0, x1, x2));
    return fminf(b0, b1);
}

// ---------------- kernel 2: windowed coherent search ----------------
extern "C" __global__ void __launch_bounds__(TS, 1)
search_kernel(float* __restrict__ out, int n, int nblk)
{
    __shared__ int   soff[NB + 1];
    __shared__ float s_bm4[P * 5];       // phase-A quarter mins (pad 5)
    __shared__ float s_bm[P];            // combined phase-A min per point
    __shared__ float s_wmax[4];
    __shared__ float rbuf[P * RPAD];     // per-point per-chunk mins
    __shared__ float buf[TS];
    __shared__ bool  amLast;

    const int tid  = threadIdx.x;
    const int bx   = blockIdx.x;
    const int b    = blockIdx.y;
    const int w    = tid >> 5;
    const int lane = tid & 31;

    for (int i = tid; i <= NB; i += TS) soff[i] = g_yoff[b][i];
    __syncthreads();

    const float4* __restrict__ Y = g_y[b];
    const int p0 = bx * P;

    // ---- phase A1: 4 threads per point scan the +-3 bucket window ----
    {
        const int i = tid & (P - 1);          // local point 0..127
        const int q = tid >> 7;               // quarter 0..3
        float4 X = g_x[b][p0 + i];
        int xb = min(max((int)((X.z - ZMIN) * ZINV), 0), NB - 1);
        int lo = max(xb - 3, 0), hi = min(xb + 3, NB - 1);
        int r0 = soff[lo], e0 = soff[hi + 1];
        float bm = 3.4e38f;
        for (int r = r0 + q; r < e0; r += 4)
            bm = fminf(bm, mval(Y[r], X.x, X.y, X.z));
        s_bm4[i * 5 + q] = bm;
    }
    __syncthreads();

    // ---- phase A2: combine quarters, handle empty windows, block max ub --
    if (tid < P) {
        const int i = tid;
        float4 X = g_x[b][p0 + i];
        const float sqx = X.x*X.x + X.y*X.y + X.z*X.z;
        float bm = fminf(fminf(s_bm4[i*5+0], s_bm4[i*5+1]),
                         fminf(s_bm4[i*5+2], s_bm4[i*5+3]));
        if (bm > 1e37f) {   // empty +-3 window (far tails): expand serially
            int xb = min(max((int)((X.z - ZMIN) * ZINV), 0), NB - 1);
            int k = 4;
            while (bm > 1e37f && (xb - k >= 0 || xb + k < NB)) {
                int bl = xb - k, bh = xb + k;
                if (bl >= 0) bm = scan_range(Y, soff[bl], soff[bl+1], X.x, X.y, X.z, bm);
                if (bh < NB) bm = scan_range(Y, soff[bh], soff[bh+1], X.x, X.y, X.z, bm);
                ++k;
            }
        }
        s_bm[i] = bm;
        float ub = sqrtf(fmaxf(bm + sqx, 0.0f));
        #pragma unroll
        for (int o = 16; o > 0; o >>= 1)
            ub = fmaxf(ub, __shfl_xor_sync(0xffffffffu, ub, o));
        if (lane == 0) s_wmax[w] = ub;
    }
    __syncthreads();

    const float rr = fmaxf(fmaxf(s_wmax[0], s_wmax[1]),
                           fmaxf(s_wmax[2], s_wmax[3]));

    // ---- window: [zmin - r, zmax + r] covers every point's true NN ----
    const float zlo = g_x[b][p0].z - rr;
    const float zhi = g_x[b][p0 + P - 1].z + rr;
    const int blo = min(max((int)floorf((zlo - ZMIN) * ZINV), 0), NB - 1);
    const int bhi = min(max((int)floorf((zhi - ZMIN) * ZINV), 0), NB - 1);
    const int r0 = soff[blo], e0 = soff[bhi + 1];
    const int L  = e0 - r0;

    // ---- phase B: 16 warp-uniform chunks x 4 register points/thread ----
    const int c0 = r0 + (L * w) / NCH;
    const int c1 = r0 + (L * (w + 1)) / NCH;

    float x0[4], x1[4], x2[4], mn[4], mn2[4];
    #pragma unroll
    for (int pt = 0; pt < 4; ++pt) {
        const int i = lane + (pt << 5);
        float4 X = g_x[b][p0 + i];
        x0[pt] = X.x; x1[pt] = X.y; x2[pt] = X.z;
        mn[pt]  = s_bm[i];          // seed with phase-A bound (superset-safe)
        mn2[pt] = 3.4e38f;
    }

    int r = c0;
    for (; r + 1 < c1; r += 2) {
        float4 qa = Y[r], qb = Y[r + 1];
        #pragma unroll
        for (int pt = 0; pt < 4; ++pt) {
            mn[pt]  = fminf(mn[pt],  mval(qa, x0[pt], x1[pt], x2[pt]));
            mn2[pt] = fminf(mn2[pt], mval(qb, x0[pt], x1[pt], x2[pt]));
        }
    }
    if (r < c1) {
        float4 qa = Y[r];
        #pragma unroll
        for (int pt = 0; pt < 4; ++pt)
            mn[pt] = fminf(mn[pt], mval(qa, x0[pt], x1[pt], x2[pt]));
    }
    #pragma unroll
    for (int pt = 0; pt < 4; ++pt)
        rbuf[(lane + (pt << 5)) * RPAD + w] = fminf(mn[pt], mn2[pt]);
    __syncthreads();

    // ---- combine chunks, write NN distance at ORIGINAL index ----
    if (tid < P) {
        const int i = tid;
        float f = 3.4e38f;
        #pragma unroll
        for (int c = 0; c < NCH; ++c) f = fminf(f, rbuf[i * RPAD + c]);
        float4 X = g_x[b][p0 + i];
        const float sqx = X.x*X.x + X.y*X.y + X.z*X.z;
        g_dist[b * n + __float_as_int(X.w)] = sqrtf(fmaxf(f + sqx, 0.0f));
    }

    __threadfence();
    __syncthreads();
    if (tid == 0) amLast = (atomicAdd(&g_count, 1) == nblk - 1);
    __syncthreads();

    if (amLast) {
        float s = 0.0f;
        const int total = NBATCH * n;
        for (int i = tid; i < total; i += TS) s += __ldcg(&g_dist[i]);
        buf[tid] = s;
        __syncthreads();
        #pragma unroll
        for (int st = TS / 2; st > 0; st >>= 1) {
            if (tid < st) buf[tid] += buf[tid + st];
            __syncthreads();
        }
        if (tid == 0) {
            out[0]  = buf[0];
            g_count = 0;           // self-reset for graph replay
        }
    }
}

extern "C" void kernel_launch(void* const* d_in, const int* in_sizes, int n_in,
                              void* d_out, int out_size)
{
    const float* set1 = (const float*)d_in[0];
    const float* set2 = (const float*)d_in[1];

    // in_sizes[0] = b * n * d = 2 * n * 3
    const int n = in_sizes[0] / (NBATCH * 3);
    const int sbx  = n / P;               // search blocks per batch
    const int nblk = sbx * NBATCH;

    bucket_kernel<<<2 * NBATCH, 1024>>>(set1, set2, n);
    dim3 grid(sbx, NBATCH);
    search_kernel<<<grid, TS>>>((float*)d_out, n, nblk);
}